// round 6
// baseline (speedup 1.0000x reference)
#include <cuda_runtime.h>
#include <cuda_bf16.h>
#include <cstdint>

#define NTOT 65536
#define DDIM 512
#define KCL  64

#define BN 128              // d-columns per CTA tile (mma N)
#define BK 32               // k rows per stage
#define DTILES 4            // DDIM / BN
#define NCHUNKS 128         // grid = 4*128 = 512 CTAs; 2048/128 = 16 iters each
#define NCTAS (DTILES * NCHUNKS)
#define ITERS 16

#define DEPTH 3
#define SF_W 72             // F stage row stride in f32 words (64 + 8 pad)
#define SH_W 136            // H stage row stride in f32 words (128 + 8 pad)
#define STAGE_W (BK * SF_W + BK * SH_W)      // 6656 words
#define SMEM_DYN (DEPTH * STAGE_W * 4)       // 79872 B

__device__ float        g_partial[KCL * DDIM];  // .bss zero; re-zeroed per call
__device__ float        g_h2sum;
__device__ unsigned int g_count;

__device__ __forceinline__ void cp16(void* s, const void* g) {
    uint32_t sa = (uint32_t)__cvta_generic_to_shared(s);
    asm volatile("cp.async.cg.shared.global [%0], [%1], 16;" :: "r"(sa), "l"(g));
}
#define CP_COMMIT() asm volatile("cp.async.commit_group;")
#define CP_WAIT(n)  asm volatile("cp.async.wait_group %0;" :: "n"(n))

__device__ __forceinline__ uint32_t to_tf32(float f) {
    uint32_t r;
    asm("cvt.rna.tf32.f32 %0, %1;" : "=r"(r) : "f"(f));
    return r;
}

__global__ __launch_bounds__(256, 2)
void k_fused(const float* __restrict__ H, const float* __restrict__ Fm,
             float* __restrict__ out) {
    extern __shared__ __align__(16) float dsm[];
    __shared__ float        redbuf[8];
    __shared__ double       sb[8];
    __shared__ unsigned int s_ticket;

    const int tid  = threadIdx.x;
    const int lane = tid & 31;
    const int wid  = tid >> 5;
    const int d0   = blockIdx.x * BN;
    const int nb0  = blockIdx.y * (ITERS * BK);

    const int wm = (wid >> 2) * 32;     // 2 warps along m (clusters)
    const int wn = (wid & 3) * 32;      // 4 warps along n (d)
    const int g  = lane >> 2;
    const int t  = lane & 3;

    // cp.async fill mapping
    const int fr = tid >> 4, fc = (tid & 15) << 2;   // F: 2 chunks/thread
    const int hr = tid >> 5, hc = (tid & 31) << 2;   // H: 4 chunks/thread

    float acc[2][4][4];
#pragma unroll
    for (int a = 0; a < 2; a++)
#pragma unroll
        for (int b = 0; b < 4; b++)
#pragma unroll
            for (int cc = 0; cc < 4; cc++) acc[a][b][cc] = 0.f;

    float h2 = 0.f;
    const bool do_h2 = (wm == 0);

    auto issue = [&](int it) {
        float* st = dsm + (it % DEPTH) * STAGE_W;
        float* sf = st;
        float* sh = st + BK * SF_W;
        const int nb = nb0 + it * BK;
#pragma unroll
        for (int j = 0; j < 2; j++) {    // F: 32 rows x 64 f32 = 512 chunks
            int r = fr + j * 16;
            cp16(sf + r * SF_W + fc, &Fm[(size_t)(nb + r) * KCL + fc]);
        }
#pragma unroll
        for (int j = 0; j < 4; j++) {    // H: 32 rows x 128 f32 = 1024 chunks
            int r = hr + j * 8;
            cp16(sh + r * SH_W + hc, &H[(size_t)(nb + r) * DDIM + d0 + hc]);
        }
        CP_COMMIT();
    };

    auto compute = [&](int it) {
        const float* st = dsm + (it % DEPTH) * STAGE_W;
        // per-thread conflict-free bases: bank = (8t + g) % 32 for both tiles
        const float* sfp = st + t * SF_W + wm + g;
        const float* shp = st + BK * SF_W + t * SH_W + wn + g;
#pragma unroll
        for (int ks = 0; ks < BK; ks += 8) {
            uint32_t a[2][4], b[4][2];
#pragma unroll
            for (int mi = 0; mi < 2; mi++) {
                const float* p = sfp + ks * SF_W + mi * 16;
                a[mi][0] = to_tf32(p[0]);
                a[mi][1] = to_tf32(p[8]);
                a[mi][2] = to_tf32(p[4 * SF_W]);
                a[mi][3] = to_tf32(p[4 * SF_W + 8]);
            }
#pragma unroll
            for (int ni = 0; ni < 4; ni++) {
                const float* p = shp + ks * SH_W + ni * 8;
                float b0 = p[0];
                float b1 = p[4 * SH_W];
                if (do_h2) h2 += b0 * b0 + b1 * b1;
                b[ni][0] = to_tf32(b0);
                b[ni][1] = to_tf32(b1);
            }
#pragma unroll
            for (int mi = 0; mi < 2; mi++)
#pragma unroll
                for (int ni = 0; ni < 4; ni++) {
                    asm volatile(
                        "mma.sync.aligned.m16n8k8.row.col.f32.tf32.tf32.f32 "
                        "{%0,%1,%2,%3}, {%4,%5,%6,%7}, {%8,%9}, {%0,%1,%2,%3};\n"
                        : "+f"(acc[mi][ni][0]), "+f"(acc[mi][ni][1]),
                          "+f"(acc[mi][ni][2]), "+f"(acc[mi][ni][3])
                        : "r"(a[mi][0]), "r"(a[mi][1]), "r"(a[mi][2]), "r"(a[mi][3]),
                          "r"(b[ni][0]), "r"(b[ni][1]));
                }
        }
    };

    // ---- multistage pipeline: depth 3, one barrier per k-block ----
    issue(0);
    issue(1);

#pragma unroll 1
    for (int it = 0; it < ITERS; ++it) {
        if (it < ITERS - 2) { CP_WAIT(1); } else { CP_WAIT(0); }
        __syncthreads();                 // stage `it` visible to all threads
        if (it + 2 < ITERS) issue(it + 2);   // refills slot consumed at it-1
        compute(it);
    }

    // ---- epilogue: packed float2 L2 atomics into partial G[m][d] ----
#pragma unroll
    for (int mi = 0; mi < 2; mi++)
#pragma unroll
        for (int ni = 0; ni < 4; ni++) {
            int m = wm + mi * 16 + g;
            int n = d0 + wn + ni * 8 + 2 * t;
            atomicAdd((float2*)&g_partial[m * DDIM + n],
                      make_float2(acc[mi][ni][0], acc[mi][ni][1]));
            atomicAdd((float2*)&g_partial[(m + 8) * DDIM + n],
                      make_float2(acc[mi][ni][2], acc[mi][ni][3]));
        }

    // ---- h2 block reduce, one atomic per CTA ----
#pragma unroll
    for (int o = 16; o > 0; o >>= 1) h2 += __shfl_xor_sync(0xffffffffu, h2, o);
    if (lane == 0) redbuf[wid] = h2;
    __syncthreads();
    if (tid == 0) {
        float s = 0.f;
#pragma unroll
        for (int w = 0; w < 8; w++) s += redbuf[w];
        atomicAdd(&g_h2sum, s);
    }

    // ---- last-CTA finalize: square-sum G, write scalar, reset state ----
    __threadfence();
    if (tid == 0) s_ticket = atomicAdd(&g_count, 1u);
    __syncthreads();
    if (s_ticket != NCTAS - 1) return;

    double s = 0.0;
    for (int i = tid; i < KCL * DDIM; i += 256) {
        float v = __ldcg(&g_partial[i]);
        s += (double)v * (double)v;
        g_partial[i] = 0.f;              // re-zero for next graph replay
    }
#pragma unroll
    for (int o = 16; o > 0; o >>= 1) s += __shfl_xor_sync(0xffffffffu, s, o);
    if (lane == 0) sb[wid] = s;
    __syncthreads();
    if (tid == 0) {
        double tot = 0.0;
#pragma unroll
        for (int w = 0; w < 8; w++) tot += sb[w];
        float h2tot = __ldcg(&g_h2sum);
        out[0] = (float)((double)h2tot - tot);
        g_h2sum = 0.f;
        g_count = 0u;
    }
}

extern "C" void kernel_launch(void* const* d_in, const int* in_sizes, int n_in,
                              void* d_out, int out_size) {
    const float* Hp;
    const float* Fp;
    if (in_sizes[0] == NTOT * DDIM) {
        Hp = (const float*)d_in[0];
        Fp = (const float*)d_in[1];
    } else {
        Hp = (const float*)d_in[1];
        Fp = (const float*)d_in[0];
    }

    cudaFuncSetAttribute(k_fused, cudaFuncAttributeMaxDynamicSharedMemorySize,
                         SMEM_DYN);
    dim3 grid(DTILES, NCHUNKS);
    k_fused<<<grid, 256, SMEM_DYN>>>(Hp, Fp, (float*)d_out);
}

// round 7
// speedup vs baseline: 1.0871x; 1.0871x over previous
#include <cuda_runtime.h>
#include <cuda_bf16.h>
#include <cstdint>

#define NTOT 65536
#define DDIM 512
#define KCL  64

#define BN 128              // d-columns per CTA tile (mma N)
#define BK 64               // k rows per stage (fat stage)
#define DTILES 4            // DDIM / BN
#define NCHUNKS 74          // grid = 4*74 = 296 CTAs = 2 CTAs/SM, one wave
#define NCTAS (DTILES * NCHUNKS)
#define KB64 (NTOT / BK)    // 1024 k-blocks total

#define DEPTH 2
#define SF_W 72             // F stage row stride in f32 words (64 + 8 pad)
#define SH_W 136            // H stage row stride in f32 words (128 + 8 pad)
#define STAGE_W (BK * SF_W + BK * SH_W)      // 13312 words = 52 KB
#define SMEM_DYN (DEPTH * STAGE_W * 4)       // 106496 B

__device__ float        g_partial[KCL * DDIM];  // .bss zero; re-zeroed per call
__device__ float        g_h2sum;
__device__ unsigned int g_count;

__device__ __forceinline__ void cp16(void* s, const void* g) {
    uint32_t sa = (uint32_t)__cvta_generic_to_shared(s);
    asm volatile("cp.async.cg.shared.global [%0], [%1], 16;" :: "r"(sa), "l"(g));
}
#define CP_COMMIT() asm volatile("cp.async.commit_group;")
#define CP_WAIT(n)  asm volatile("cp.async.wait_group %0;" :: "n"(n))

__device__ __forceinline__ uint32_t to_tf32(float f) {
    uint32_t r;
    asm("cvt.rna.tf32.f32 %0, %1;" : "=r"(r) : "f"(f));
    return r;
}

__global__ __launch_bounds__(256, 2)
void k_fused(const float* __restrict__ H, const float* __restrict__ Fm,
             float* __restrict__ out) {
    extern __shared__ __align__(16) float dsm[];
    __shared__ float        redbuf[8];
    __shared__ double       sb[8];
    __shared__ unsigned int s_ticket;

    const int tid  = threadIdx.x;
    const int lane = tid & 31;
    const int wid  = tid >> 5;
    const int d0   = blockIdx.x * BN;
    const int c    = blockIdx.y;

    // 1024 fat k-blocks over 74 chunks: chunks 0..61 get 14, 62..73 get 13
    const int kb_start = c * 13 + (c < 62 ? c : 62);
    const int ITERS    = 13 + (c < 62 ? 1 : 0);
    const int nb0      = kb_start * BK;

    const int wm = (wid >> 2) * 32;     // 2 warps along m (clusters)
    const int wn = (wid & 3) * 32;      // 4 warps along n (d)
    const int g  = lane >> 2;
    const int t  = lane & 3;

    // cp.async fill mapping (64 rows per stage)
    const int fr = tid >> 4, fc = (tid & 15) << 2;   // F: 4 chunks/thread
    const int hr = tid >> 5, hc = (tid & 31) << 2;   // H: 8 chunks/thread

    float acc[2][4][4];
#pragma unroll
    for (int a = 0; a < 2; a++)
#pragma unroll
        for (int b = 0; b < 4; b++)
#pragma unroll
            for (int cc = 0; cc < 4; cc++) acc[a][b][cc] = 0.f;

    float h2 = 0.f;
    const bool do_h2 = (wm == 0);       // wm==0 warps touch every H element once

    auto issue = [&](int it) {
        float* st = dsm + (it & 1) * STAGE_W;
        float* sf = st;
        float* sh = st + BK * SF_W;
        const int nb = nb0 + it * BK;
#pragma unroll
        for (int j = 0; j < 4; j++) {    // F: 64 rows x 64 f32 = 1024 chunks
            int r = fr + j * 16;
            cp16(sf + r * SF_W + fc, &Fm[(size_t)(nb + r) * KCL + fc]);
        }
#pragma unroll
        for (int j = 0; j < 8; j++) {    // H: 64 rows x 128 f32 = 2048 chunks
            int r = hr + j * 8;
            cp16(sh + r * SH_W + hc, &H[(size_t)(nb + r) * DDIM + d0 + hc]);
        }
        CP_COMMIT();
    };

    auto compute = [&](int it) {
        const float* st = dsm + (it & 1) * STAGE_W;
        // conflict-free bases: bank = (8t + g) % 32 for both tiles
        const float* sfp = st + t * SF_W + wm + g;
        const float* shp = st + BK * SF_W + t * SH_W + wn + g;
#pragma unroll
        for (int ks = 0; ks < BK; ks += 8) {
            uint32_t a[2][4], b[4][2];
#pragma unroll
            for (int mi = 0; mi < 2; mi++) {
                const float* p = sfp + ks * SF_W + mi * 16;
                a[mi][0] = to_tf32(p[0]);
                a[mi][1] = to_tf32(p[8]);
                a[mi][2] = to_tf32(p[4 * SF_W]);
                a[mi][3] = to_tf32(p[4 * SF_W + 8]);
            }
#pragma unroll
            for (int ni = 0; ni < 4; ni++) {
                const float* p = shp + ks * SH_W + ni * 8;
                float b0 = p[0];
                float b1 = p[4 * SH_W];
                if (do_h2) h2 += b0 * b0 + b1 * b1;
                b[ni][0] = to_tf32(b0);
                b[ni][1] = to_tf32(b1);
            }
#pragma unroll
            for (int mi = 0; mi < 2; mi++)
#pragma unroll
                for (int ni = 0; ni < 4; ni++) {
                    asm volatile(
                        "mma.sync.aligned.m16n8k8.row.col.f32.tf32.tf32.f32 "
                        "{%0,%1,%2,%3}, {%4,%5,%6,%7}, {%8,%9}, {%0,%1,%2,%3};\n"
                        : "+f"(acc[mi][ni][0]), "+f"(acc[mi][ni][1]),
                          "+f"(acc[mi][ni][2]), "+f"(acc[mi][ni][3])
                        : "r"(a[mi][0]), "r"(a[mi][1]), "r"(a[mi][2]), "r"(a[mi][3]),
                          "r"(b[ni][0]), "r"(b[ni][1]));
                }
        }
    };

    // ---- pipeline: DEPTH=2 fat stages, prefetch distance 1 ----
    issue(0);

#pragma unroll 1
    for (int it = 0; it < ITERS; ++it) {
        if (it + 1 < ITERS) {
            issue(it + 1);   // buf (it+1)&1: consumed at it-1, guarded by tail barrier
            CP_WAIT(1);      // stage `it` complete (own groups)
        } else {
            CP_WAIT(0);
        }
        __syncthreads();     // stage `it` visible to all threads
        compute(it);
        __syncthreads();     // compute(it) done before issue(it+2) overwrites buf
    }

    // ---- epilogue: packed float2 L2 atomics into partial G[m][d] ----
#pragma unroll
    for (int mi = 0; mi < 2; mi++)
#pragma unroll
        for (int ni = 0; ni < 4; ni++) {
            int m = wm + mi * 16 + g;
            int n = d0 + wn + ni * 8 + 2 * t;
            atomicAdd((float2*)&g_partial[m * DDIM + n],
                      make_float2(acc[mi][ni][0], acc[mi][ni][1]));
            atomicAdd((float2*)&g_partial[(m + 8) * DDIM + n],
                      make_float2(acc[mi][ni][2], acc[mi][ni][3]));
        }

    // ---- h2 block reduce, one atomic per CTA ----
#pragma unroll
    for (int o = 16; o > 0; o >>= 1) h2 += __shfl_xor_sync(0xffffffffu, h2, o);
    if (lane == 0) redbuf[wid] = h2;
    __syncthreads();
    if (tid == 0) {
        float s = 0.f;
#pragma unroll
        for (int w = 0; w < 8; w++) s += redbuf[w];
        atomicAdd(&g_h2sum, s);
    }

    // ---- last-CTA finalize: square-sum G, write scalar, reset state ----
    __threadfence();
    if (tid == 0) s_ticket = atomicAdd(&g_count, 1u);
    __syncthreads();
    if (s_ticket != NCTAS - 1) return;

    double s = 0.0;
    for (int i = tid; i < KCL * DDIM; i += 256) {
        float v = __ldcg(&g_partial[i]);
        s += (double)v * (double)v;
        g_partial[i] = 0.f;              // re-zero for next graph replay
    }
#pragma unroll
    for (int o = 16; o > 0; o >>= 1) s += __shfl_xor_sync(0xffffffffu, s, o);
    if (lane == 0) sb[wid] = s;
    __syncthreads();
    if (tid == 0) {
        double tot = 0.0;
#pragma unroll
        for (int w = 0; w < 8; w++) tot += sb[w];
        float h2tot = __ldcg(&g_h2sum);
        out[0] = (float)((double)h2tot - tot);
        g_h2sum = 0.f;
        g_count = 0u;
    }
}

extern "C" void kernel_launch(void* const* d_in, const int* in_sizes, int n_in,
                              void* d_out, int out_size) {
    const float* Hp;
    const float* Fp;
    if (in_sizes[0] == NTOT * DDIM) {
        Hp = (const float*)d_in[0];
        Fp = (const float*)d_in[1];
    } else {
        Hp = (const float*)d_in[1];
        Fp = (const float*)d_in[0];
    }

    cudaFuncSetAttribute(k_fused, cudaFuncAttributeMaxDynamicSharedMemorySize,
                         SMEM_DYN);
    dim3 grid(DTILES, NCHUNKS);
    k_fused<<<grid, 256, SMEM_DYN>>>(Hp, Fp, (float*)d_out);
}

// round 8
// speedup vs baseline: 1.1692x; 1.0754x over previous
#include <cuda_runtime.h>
#include <cuda_bf16.h>
#include <cstdint>

#define NTOT 65536
#define DDIM 512
#define KCL  64

#define BN 128              // d-columns per CTA tile (mma N)
#define BK 64               // k rows per stage
#define DTILES 4            // DDIM / BN
#define NCHUNKS 74          // grid = 4*74 = 296 CTAs = 2 CTAs/SM, one wave
#define NCTAS (DTILES * NCHUNKS)

#define SF_W 72             // F stage row stride, f32 words (64 + 8 pad, 288B)
#define SH_W 136            // H stage row stride, f32 words (128 + 8 pad, 544B)
#define STAGE_W (BK * SF_W + BK * SH_W)      // 13312 words = 52 KB
#define SMEM_DYN (2 * STAGE_W * 4)           // 106496 B
#define STAGE_BYTES (BK * 64 * 4 + BK * 128 * 4)   // 49152 real bytes per stage

__device__ float        g_partial[KCL * DDIM];  // .bss zero; re-zeroed per call
__device__ float        g_h2sum;
__device__ unsigned int g_count;

__device__ __forceinline__ uint32_t smem_u32(const void* p) {
    return (uint32_t)__cvta_generic_to_shared(p);
}

__device__ __forceinline__ uint32_t to_tf32(float f) {
    uint32_t r;
    asm("cvt.rna.tf32.f32 %0, %1;" : "=r"(r) : "f"(f));
    return r;
}

__device__ __forceinline__ void bulk_cp(uint32_t dst, const void* src,
                                        uint32_t bytes, uint32_t mbar) {
    asm volatile(
        "cp.async.bulk.shared::cta.global.mbarrier::complete_tx::bytes "
        "[%0], [%1], %2, [%3];"
        :: "r"(dst), "l"(src), "r"(bytes), "r"(mbar) : "memory");
}

__device__ __forceinline__ void mbar_arrive_tx(uint32_t mbar, uint32_t bytes) {
    asm volatile("mbarrier.arrive.expect_tx.shared::cta.b64 _, [%0], %1;"
                 :: "r"(mbar), "r"(bytes) : "memory");
}

__device__ __forceinline__ void mbar_wait(uint32_t addr, uint32_t parity) {
    asm volatile(
        "{\n\t"
        ".reg .pred P1;\n\t"
        "WL_%=:\n\t"
        "mbarrier.try_wait.parity.acquire.cta.shared::cta.b64 P1, [%0], %1, 0x989680;\n\t"
        "@P1 bra.uni WD_%=;\n\t"
        "bra.uni WL_%=;\n\t"
        "WD_%=:\n\t"
        "}" :: "r"(addr), "r"(parity) : "memory");
}

__global__ __launch_bounds__(256, 2)
void k_fused(const float* __restrict__ H, const float* __restrict__ Fm,
             float* __restrict__ out) {
    extern __shared__ __align__(16) float dsm[];
    __shared__ __align__(8) uint64_t mbar[2];
    __shared__ float        redbuf[8];
    __shared__ double       sb[8];
    __shared__ unsigned int s_ticket;

    const int tid  = threadIdx.x;
    const int lane = tid & 31;
    const int wid  = tid >> 5;
    const int d0   = blockIdx.x * BN;
    const int c    = blockIdx.y;

    // 1024 k-blocks over 74 chunks: chunks 0..61 get 14, 62..73 get 13
    const int kb_start = c * 13 + (c < 62 ? c : 62);
    const int ITERS    = 13 + (c < 62 ? 1 : 0);
    const int nb0      = kb_start * BK;

    const int wm = (wid >> 2) * 32;     // 2 warps along m (clusters)
    const int wn = (wid & 3) * 32;      // 4 warps along n (d)
    const int g  = lane >> 2;
    const int t  = lane & 3;

    if (tid < 2) {
        asm volatile("mbarrier.init.shared::cta.b64 [%0], %1;"
                     :: "r"(smem_u32(&mbar[tid])), "r"(128u) : "memory");
    }
    __syncthreads();
    const uint32_t mb[2] = { smem_u32(&mbar[0]), smem_u32(&mbar[1]) };

    float acc[2][4][4];
#pragma unroll
    for (int a = 0; a < 2; a++)
#pragma unroll
        for (int b = 0; b < 4; b++)
#pragma unroll
            for (int cc = 0; cc < 4; cc++) acc[a][b][cc] = 0.f;

    float h2 = 0.f;
    const bool do_h2 = (wm == 0);       // wid 0..3 cover every H element once

    // ---- bulk-copy producer: 128 threads, one row-copy each ----
    auto issue = [&](int it) {
        if (tid >= 128) return;
        const int buf = it & 1;
        const int nb  = nb0 + it * BK;
        uint32_t stage = smem_u32(dsm) + buf * (STAGE_W * 4);
        if (tid < 64) {
            // F row `tid`: 64 f32 = 256 B
            mbar_arrive_tx(mb[buf], 256u);
            bulk_cp(stage + (uint32_t)tid * (SF_W * 4),
                    &Fm[(size_t)(nb + tid) * KCL], 256u, mb[buf]);
        } else {
            // H row `tid-64`: 128 f32 = 512 B
            const int r = tid - 64;
            mbar_arrive_tx(mb[buf], 512u);
            bulk_cp(stage + (uint32_t)(BK * SF_W * 4) + (uint32_t)r * (SH_W * 4),
                    &H[(size_t)(nb + r) * DDIM + d0], 512u, mb[buf]);
        }
    };

    auto compute = [&](int it) {
        const float* st = dsm + (it & 1) * STAGE_W;
        // conflict-free bases: bank = (8t + g) % 32 for both tiles
        const float* sfp = st + t * SF_W + wm + g;
        const float* shp = st + BK * SF_W + t * SH_W + wn + g;
#pragma unroll
        for (int ks = 0; ks < BK; ks += 8) {
            uint32_t a[2][4], b[4][2];
#pragma unroll
            for (int mi = 0; mi < 2; mi++) {
                const float* p = sfp + ks * SF_W + mi * 16;
                a[mi][0] = to_tf32(p[0]);
                a[mi][1] = to_tf32(p[8]);
                a[mi][2] = to_tf32(p[4 * SF_W]);
                a[mi][3] = to_tf32(p[4 * SF_W + 8]);
            }
#pragma unroll
            for (int ni = 0; ni < 4; ni++) {
                const float* p = shp + ks * SH_W + ni * 8;
                float b0 = p[0];
                float b1 = p[4 * SH_W];
                if (do_h2) h2 += b0 * b0 + b1 * b1;
                b[ni][0] = to_tf32(b0);
                b[ni][1] = to_tf32(b1);
            }
#pragma unroll
            for (int mi = 0; mi < 2; mi++)
#pragma unroll
                for (int ni = 0; ni < 4; ni++) {
                    asm volatile(
                        "mma.sync.aligned.m16n8k8.row.col.f32.tf32.tf32.f32 "
                        "{%0,%1,%2,%3}, {%4,%5,%6,%7}, {%8,%9}, {%0,%1,%2,%3};\n"
                        : "+f"(acc[mi][ni][0]), "+f"(acc[mi][ni][1]),
                          "+f"(acc[mi][ni][2]), "+f"(acc[mi][ni][3])
                        : "r"(a[mi][0]), "r"(a[mi][1]), "r"(a[mi][2]), "r"(a[mi][3]),
                          "r"(b[ni][0]), "r"(b[ni][1]));
                }
        }
    };

    // ---- pipeline: 2 buffers, bulk-copy + mbarrier, one barrier per stage ----
    int ph[2] = {0, 0};
    issue(0);

#pragma unroll 1
    for (int it = 0; it < ITERS; ++it) {
        const int buf = it & 1;
        if (it + 1 < ITERS) issue(it + 1);   // other buffer; consumed at it-1
        mbar_wait(mb[buf], ph[buf]);
        ph[buf] ^= 1;
        compute(it);
        __syncthreads();                     // reuse guard before issue(it+2)
    }

    // ---- epilogue: packed float2 L2 atomics into partial G[m][d] ----
#pragma unroll
    for (int mi = 0; mi < 2; mi++)
#pragma unroll
        for (int ni = 0; ni < 4; ni++) {
            int m = wm + mi * 16 + g;
            int n = d0 + wn + ni * 8 + 2 * t;
            atomicAdd((float2*)&g_partial[m * DDIM + n],
                      make_float2(acc[mi][ni][0], acc[mi][ni][1]));
            atomicAdd((float2*)&g_partial[(m + 8) * DDIM + n],
                      make_float2(acc[mi][ni][2], acc[mi][ni][3]));
        }

    // ---- h2 block reduce, one atomic per CTA ----
#pragma unroll
    for (int o = 16; o > 0; o >>= 1) h2 += __shfl_xor_sync(0xffffffffu, h2, o);
    if (lane == 0) redbuf[wid] = h2;
    __syncthreads();
    if (tid == 0) {
        float s = 0.f;
#pragma unroll
        for (int w = 0; w < 8; w++) s += redbuf[w];
        atomicAdd(&g_h2sum, s);
    }

    // ---- last-CTA finalize: square-sum G, write scalar, reset state ----
    __threadfence();
    if (tid == 0) s_ticket = atomicAdd(&g_count, 1u);
    __syncthreads();
    if (s_ticket != NCTAS - 1) return;

    double s = 0.0;
    for (int i = tid; i < KCL * DDIM; i += 256) {
        float v = __ldcg(&g_partial[i]);
        s += (double)v * (double)v;
        g_partial[i] = 0.f;              // re-zero for next graph replay
    }
#pragma unroll
    for (int o = 16; o > 0; o >>= 1) s += __shfl_xor_sync(0xffffffffu, s, o);
    if (lane == 0) sb[wid] = s;
    __syncthreads();
    if (tid == 0) {
        double tot = 0.0;
#pragma unroll
        for (int w = 0; w < 8; w++) tot += sb[w];
        float h2tot = __ldcg(&g_h2sum);
        out[0] = (float)((double)h2tot - tot);
        g_h2sum = 0.f;
        g_count = 0u;
    }
}

extern "C" void kernel_launch(void* const* d_in, const int* in_sizes, int n_in,
                              void* d_out, int out_size) {
    const float* Hp;
    const float* Fp;
    if (in_sizes[0] == NTOT * DDIM) {
        Hp = (const float*)d_in[0];
        Fp = (const float*)d_in[1];
    } else {
        Hp = (const float*)d_in[1];
        Fp = (const float*)d_in[0];
    }

    cudaFuncSetAttribute(k_fused, cudaFuncAttributeMaxDynamicSharedMemorySize,
                         SMEM_DYN);
    dim3 grid(DTILES, NCHUNKS);
    k_fused<<<grid, 256, SMEM_DYN>>>(Hp, Fp, (float*)d_out);
}

// round 9
// speedup vs baseline: 1.3457x; 1.1510x over previous
#include <cuda_runtime.h>
#include <cuda_bf16.h>
#include <cstdint>

#define NTOT 65536
#define DDIM 512
#define KCL  64

#define BN 128              // d-columns per CTA tile
#define BK 32               // k rows per stage
#define DTILES 4            // DDIM / BN
#define NCHUNKS 74          // grid = 4*74 = 296 CTAs = 2 CTAs/SM, one wave
#define NCTAS (DTILES * NCHUNKS)

#define SF_B 144            // F smem row stride bytes (64 bf16 = 128 + 16 pad)
#define SH_B 272            // H smem row stride bytes (128 bf16 = 256 + 16 pad)

__device__ float        g_partial[KCL * DDIM];  // .bss zero; re-zeroed per call
__device__ float        g_h2sum;
__device__ unsigned int g_count;

__device__ __forceinline__ uint32_t smem_u32(const void* p) {
    return (uint32_t)__cvta_generic_to_shared(p);
}

__device__ __forceinline__ uint32_t pack_bf16(float lo, float hi) {
    uint32_t r;
    asm("cvt.rn.bf16x2.f32 %0, %1, %2;" : "=r"(r) : "f"(hi), "f"(lo));
    return r;
}

__device__ __forceinline__ void ldsm4t(uint32_t* r, uint32_t addr) {
    asm volatile(
        "ldmatrix.sync.aligned.m8n8.x4.trans.shared.b16 {%0,%1,%2,%3}, [%4];"
        : "=r"(r[0]), "=r"(r[1]), "=r"(r[2]), "=r"(r[3]) : "r"(addr));
}

__global__ __launch_bounds__(256, 2)
void k_fused(const float* __restrict__ H, const float* __restrict__ Fm,
             float* __restrict__ out) {
    // smem tiles stay in gmem order: rows = k, padded strides for LDSM/STS
    __shared__ __align__(16) char Fs[2][BK * SF_B];   // 2 x 4608 B
    __shared__ __align__(16) char Hs[2][BK * SH_B];   // 2 x 8704 B
    __shared__ float        redbuf[8];
    __shared__ double       sb[8];
    __shared__ unsigned int s_ticket;

    const int tid  = threadIdx.x;
    const int lane = tid & 31;
    const int wid  = tid >> 5;
    const int d0   = blockIdx.x * BN;
    const int c    = blockIdx.y;

    // 2048 k-blocks over 74 chunks: chunks 0..49 get 28, 50..73 get 27
    const int kb_start = c * 27 + (c < 50 ? c : 50);
    const int ITERS    = 27 + (c < 50 ? 1 : 0);
    const int nb0      = kb_start * BK;

    const int wm = (wid >> 2) * 32;     // 2 warp groups along m
    const int wn = (wid & 3) * 32;      // 4 warps along n (d)
    const int g  = lane >> 2;
    const int t  = lane & 3;

    // producer mapping: lanes 0-15 -> k even, 16-31 -> k odd (per half-warp STS phase)
    const int lk = lane >> 4;           // k offset within pair
    const int lq = lane & 15;           // 16B quad index

    // LDSM per-lane offsets (bytes), derived from mat = lane/8 assignment
    const uint32_t a_lane = (uint32_t)(((lane >> 4) & 1) * (8 * SF_B)
                                       + (lane & 7) * SF_B
                                       + ((lane >> 3) & 1) * 16);
    const uint32_t b_lane = (uint32_t)(((lane >> 3) & 1) * (8 * SH_B)
                                       + (lane & 7) * SH_B
                                       + ((lane >> 4) & 1) * 16);

    float acc[2][4][4];
#pragma unroll
    for (int a = 0; a < 2; a++)
#pragma unroll
        for (int b = 0; b < 4; b++)
#pragma unroll
            for (int cc = 0; cc < 4; cc++) acc[a][b][cc] = 0.f;

    float h2 = 0.f;

    float4 rf[2], rh[2][2];

    auto gload = [&](int nb) {
#pragma unroll
        for (int j = 0; j < 2; j++) {
            const int k = nb + 2 * (wid + 8 * j) + lk;
            rf[j] = *(const float4*)&Fm[(size_t)k * KCL + lq * 4];
#pragma unroll
            for (int s = 0; s < 2; s++)
                rh[j][s] = *(const float4*)&H[(size_t)k * DDIM + d0 + s * 64 + lq * 4];
        }
    };

    auto sstore = [&](int buf) {
        char* fb = Fs[buf];
        char* hb = Hs[buf];
#pragma unroll
        for (int j = 0; j < 2; j++) {
            const int k = 2 * (wid + 8 * j) + lk;
            uint2 fv = make_uint2(pack_bf16(rf[j].x, rf[j].y),
                                  pack_bf16(rf[j].z, rf[j].w));
            *(uint2*)(fb + k * SF_B + lq * 8) = fv;
#pragma unroll
            for (int s = 0; s < 2; s++) {
                float4 h4 = rh[j][s];
                uint2 hv = make_uint2(pack_bf16(h4.x, h4.y),
                                      pack_bf16(h4.z, h4.w));
                *(uint2*)(hb + k * SH_B + s * 128 + lq * 8) = hv;
                h2 = fmaf(h4.x, h4.x, h2);
                h2 = fmaf(h4.y, h4.y, h2);
                h2 = fmaf(h4.z, h4.z, h2);
                h2 = fmaf(h4.w, h4.w, h2);
            }
        }
    };

    auto compute = [&](int buf) {
        const uint32_t aBase = smem_u32(Fs[buf]) + (uint32_t)(wm * 2) + a_lane;
        const uint32_t bBase = smem_u32(Hs[buf]) + (uint32_t)(wn * 2) + b_lane;
#pragma unroll
        for (int ks = 0; ks < 2; ks++) {          // two k16 steps per BK=32
            uint32_t a[2][4], b[2][4];
            ldsm4t(a[0], aBase + ks * (16 * SF_B));
            ldsm4t(a[1], aBase + ks * (16 * SF_B) + 32);      // m + 16
            ldsm4t(b[0], bBase + ks * (16 * SH_B));
            ldsm4t(b[1], bBase + ks * (16 * SH_B) + 32);      // n + 16
#pragma unroll
            for (int mi = 0; mi < 2; mi++)
#pragma unroll
                for (int ni = 0; ni < 4; ni++) {
                    const uint32_t b0 = b[ni >> 1][(ni & 1) * 2];
                    const uint32_t b1 = b[ni >> 1][(ni & 1) * 2 + 1];
                    asm volatile(
                        "mma.sync.aligned.m16n8k16.row.col.f32.bf16.bf16.f32 "
                        "{%0,%1,%2,%3}, {%4,%5,%6,%7}, {%8,%9}, {%0,%1,%2,%3};\n"
                        : "+f"(acc[mi][ni][0]), "+f"(acc[mi][ni][1]),
                          "+f"(acc[mi][ni][2]), "+f"(acc[mi][ni][3])
                        : "r"(a[mi][0]), "r"(a[mi][1]), "r"(a[mi][2]), "r"(a[mi][3]),
                          "r"(b0), "r"(b1));
                }
        }
    };

    // ---- pipeline: double buffer, register prefetch distance 1 ----
    gload(nb0);
    sstore(0);
    __syncthreads();

#pragma unroll 1
    for (int it = 0; it < ITERS; ++it) {
        const int buf = it & 1;
        if (it + 1 < ITERS) gload(nb0 + (it + 1) * BK);
        compute(buf);
        if (it + 1 < ITERS) sstore(buf ^ 1);
        __syncthreads();
    }

    // ---- epilogue: packed float2 L2 atomics into partial G[m][d] ----
#pragma unroll
    for (int mi = 0; mi < 2; mi++)
#pragma unroll
        for (int ni = 0; ni < 4; ni++) {
            int m = wm + mi * 16 + g;
            int n = d0 + wn + ni * 8 + 2 * t;
            atomicAdd((float2*)&g_partial[m * DDIM + n],
                      make_float2(acc[mi][ni][0], acc[mi][ni][1]));
            atomicAdd((float2*)&g_partial[(m + 8) * DDIM + n],
                      make_float2(acc[mi][ni][2], acc[mi][ni][3]));
        }

    // ---- h2 block reduce, one atomic per CTA ----
#pragma unroll
    for (int o = 16; o > 0; o >>= 1) h2 += __shfl_xor_sync(0xffffffffu, h2, o);
    if (lane == 0) redbuf[wid] = h2;
    __syncthreads();
    if (tid == 0) {
        float s = 0.f;
#pragma unroll
        for (int w = 0; w < 8; w++) s += redbuf[w];
        atomicAdd(&g_h2sum, s);
    }

    // ---- last-CTA finalize: square-sum G, write scalar, reset state ----
    __threadfence();
    if (tid == 0) s_ticket = atomicAdd(&g_count, 1u);
    __syncthreads();
    if (s_ticket != NCTAS - 1) return;

    double s = 0.0;
    for (int i = tid; i < KCL * DDIM; i += 256) {
        float v = __ldcg(&g_partial[i]);
        s += (double)v * (double)v;
        g_partial[i] = 0.f;              // re-zero for next graph replay
    }
#pragma unroll
    for (int o = 16; o > 0; o >>= 1) s += __shfl_xor_sync(0xffffffffu, s, o);
    if (lane == 0) sb[wid] = s;
    __syncthreads();
    if (tid == 0) {
        double tot = 0.0;
#pragma unroll
        for (int w = 0; w < 8; w++) tot += sb[w];
        float h2tot = __ldcg(&g_h2sum);
        out[0] = (float)((double)h2tot - tot);
        g_h2sum = 0.f;
        g_count = 0u;
    }
}

extern "C" void kernel_launch(void* const* d_in, const int* in_sizes, int n_in,
                              void* d_out, int out_size) {
    const float* Hp;
    const float* Fp;
    if (in_sizes[0] == NTOT * DDIM) {
        Hp = (const float*)d_in[0];
        Fp = (const float*)d_in[1];
    } else {
        Hp = (const float*)d_in[1];
        Fp = (const float*)d_in[0];
    }

    dim3 grid(DTILES, NCHUNKS);
    k_fused<<<grid, 256>>>(Hp, Fp, (float*)d_out);
}